// round 2
// baseline (speedup 1.0000x reference)
#include <cuda_runtime.h>
#include <cuda_bf16.h>
#include <cstdint>
#include <cstddef>

// ---------------------------------------------------------------------------
// Attention: B=32, N=1024, D=512, fp32.
// tf32 mma.sync GEMMs, cvt-free mainloops (producer-side rounding),
// k-permuted smem layout for LDS.64 fragment loads.
// ---------------------------------------------------------------------------

#define B_BATCH 32
#define N_SEQ   1024
#define DIM     512
#define M_TOT   (B_BATCH * N_SEQ)          // 32768
#define QKV_STRIDE ((size_t)M_TOT * DIM)   // per q/k/v plane
#define BATCH_QKV  ((size_t)N_SEQ * DIM)
#define BATCH_S    ((size_t)N_SEQ * N_SEQ)

// Scratch (static device globals)
__device__ float g_x[QKV_STRIDE];          // tf32-rounded X
__device__ float g_w[3 * DIM * DIM];       // tf32-rounded Wq,Wk,Wv
__device__ float g_qkv[3 * QKV_STRIDE];    // q,k plain; v stored transposed per batch [DIM][N_SEQ]
__device__ float g_s[B_BATCH * BATCH_S];   // scores / probs

// ---- PTX helpers ----------------------------------------------------------
__device__ __forceinline__ uint32_t f2tf(float x) {
    uint32_t r;
    asm("cvt.rna.tf32.f32 %0, %1;" : "=r"(r) : "f"(x));
    return r;
}
__device__ __forceinline__ float roundtf(float x) { return __uint_as_float(f2tf(x)); }

__device__ __forceinline__ void mma_16x8x8(float* c, const uint32_t* a,
                                           uint32_t b0, uint32_t b1) {
    asm volatile(
        "mma.sync.aligned.m16n8k8.row.col.f32.tf32.tf32.f32 "
        "{%0,%1,%2,%3}, {%4,%5,%6,%7}, {%8,%9}, {%0,%1,%2,%3};"
        : "+f"(c[0]), "+f"(c[1]), "+f"(c[2]), "+f"(c[3])
        : "r"(a[0]), "r"(a[1]), "r"(a[2]), "r"(a[3]), "r"(b0), "r"(b1));
}

// ---- Tiled NT GEMM --------------------------------------------------------
// C[M,N] = alpha * A[M,K] * B[N,K]^T, both row-major K-contiguous.
// Block 128x128x32, 256 threads, 8 warps (4m x 2n), warp 32x64.
// Smem k-permutation: element k = 4a+t stored at column 8t+a (stride 34).
// Thread (g,t4) mma fragment k-pair {8ks+t4, 8ks+t4+4} -> adjacent cols
// {8t4+2ks, 8t4+2ks+1} => LDS.64, conflict-free at stride 34.
#define TSTRIDE 34
#define TBUF    (128 * TSTRIDE)            // 4352 floats
#define SMEM_BYTES (4 * TBUF * 4)          // 2 bufs x (A+B) = 69632 B

// EPI: 0 = plain store, 1 = tf32-rounded store, 2 = tf32-rounded transposed
// store into per-batch [DIM][N_SEQ] plane (for V^T).
template<int EPI>
__device__ __forceinline__ void gemm_nt(const float* __restrict__ A,
                                        const float* __restrict__ B,
                                        float* __restrict__ C,
                                        int lda, int ldb, int ldc,
                                        int K, float alpha) {
    extern __shared__ float smem[];
    float* As = smem;
    float* Bs = smem + 2 * TBUF;

    const int tid  = threadIdx.x;
    const int bm   = blockIdx.x * 128;
    const int bn   = blockIdx.y * 128;
    const int lane = tid & 31;
    const int wid  = tid >> 5;
    const int wm0  = (wid & 3) * 32;
    const int wn0  = (wid >> 2) * 64;
    const int g    = lane >> 2;
    const int t4   = lane & 3;

    // staging mapping: thread loads float4 at (row = tid>>3 + 32i, k = 4a..4a+3), a = tid&7
    const int srow = tid >> 3;
    const int sa   = tid & 7;

    float acc[2][8][4];
#pragma unroll
    for (int i = 0; i < 2; i++)
#pragma unroll
        for (int j = 0; j < 8; j++)
#pragma unroll
            for (int r = 0; r < 4; r++) acc[i][j][r] = 0.0f;

    float4 ra[4], rb[4];

    auto ldg = [&](int kt) {
        const float* Ap = A + (size_t)(bm + srow) * lda + kt * 32 + sa * 4;
        const float* Bp = B + (size_t)(bn + srow) * ldb + kt * 32 + sa * 4;
#pragma unroll
        for (int i = 0; i < 4; i++) {
            ra[i] = *(const float4*)(Ap + (size_t)i * 32 * lda);
            rb[i] = *(const float4*)(Bp + (size_t)i * 32 * ldb);
        }
    };
    auto sts = [&](int buf) {
        float* Ad = As + buf * TBUF;
        float* Bd = Bs + buf * TBUF;
#pragma unroll
        for (int i = 0; i < 4; i++) {
            const int r = (srow + i * 32) * TSTRIDE + sa;   // col 8t + a
            Ad[r + 0]  = ra[i].x;
            Ad[r + 8]  = ra[i].y;
            Ad[r + 16] = ra[i].z;
            Ad[r + 24] = ra[i].w;
            Bd[r + 0]  = rb[i].x;
            Bd[r + 8]  = rb[i].y;
            Bd[r + 16] = rb[i].z;
            Bd[r + 24] = rb[i].w;
        }
    };
    auto compute = [&](int buf) {
        const float* Ab = As + buf * TBUF;
        const float* Bb = Bs + buf * TBUF;
#pragma unroll
        for (int ks = 0; ks < 4; ks++) {
            uint32_t af[2][4];
#pragma unroll
            for (int i = 0; i < 2; i++) {
                const int r = wm0 + i * 16 + g;
                float2 lo = *(const float2*)(Ab + r * TSTRIDE + 8 * t4 + 2 * ks);
                float2 hi = *(const float2*)(Ab + (r + 8) * TSTRIDE + 8 * t4 + 2 * ks);
                af[i][0] = __float_as_uint(lo.x);
                af[i][1] = __float_as_uint(hi.x);
                af[i][2] = __float_as_uint(lo.y);
                af[i][3] = __float_as_uint(hi.y);
            }
#pragma unroll
            for (int j = 0; j < 8; j++) {
                const int n = wn0 + j * 8 + g;
                float2 bv = *(const float2*)(Bb + n * TSTRIDE + 8 * t4 + 2 * ks);
                const uint32_t b0 = __float_as_uint(bv.x);
                const uint32_t b1 = __float_as_uint(bv.y);
                mma_16x8x8(acc[0][j], af[0], b0, b1);
                mma_16x8x8(acc[1][j], af[1], b0, b1);
            }
        }
    };

    const int KT = K >> 5;
    ldg(0); sts(0); __syncthreads();
    for (int kt = 0; kt < KT; kt++) {
        const int buf = kt & 1;
        if (kt + 1 < KT) ldg(kt + 1);
        compute(buf);
        if (kt + 1 < KT) sts(buf ^ 1);
        __syncthreads();
    }

    // epilogue
#pragma unroll
    for (int i = 0; i < 2; i++) {
#pragma unroll
        for (int j = 0; j < 8; j++) {
            const int r0 = bm + wm0 + i * 16 + g;
            const int c0 = bn + wn0 + j * 8 + 2 * t4;
            float v00 = acc[i][j][0] * alpha, v01 = acc[i][j][1] * alpha;
            float v10 = acc[i][j][2] * alpha, v11 = acc[i][j][3] * alpha;
            if (EPI == 0) {
                *(float2*)&C[(size_t)r0 * ldc + c0] = make_float2(v00, v01);
                *(float2*)&C[(size_t)(r0 + 8) * ldc + c0] = make_float2(v10, v11);
            } else if (EPI == 1) {
                *(float2*)&C[(size_t)r0 * ldc + c0] =
                    make_float2(roundtf(v00), roundtf(v01));
                *(float2*)&C[(size_t)(r0 + 8) * ldc + c0] =
                    make_float2(roundtf(v10), roundtf(v11));
            } else {
                // transposed per-batch store: row index = b*1024+n, col = dim
                const size_t b0 = (size_t)(r0 >> 10) * BATCH_QKV;
                const int n0 = r0 & 1023;
                C[b0 + (size_t)c0 * N_SEQ + n0]           = roundtf(v00);
                C[b0 + (size_t)(c0 + 1) * N_SEQ + n0]     = roundtf(v01);
                C[b0 + (size_t)c0 * N_SEQ + n0 + 8]       = roundtf(v10);
                C[b0 + (size_t)(c0 + 1) * N_SEQ + n0 + 8] = roundtf(v11);
            }
        }
    }
}

// ---- kernels --------------------------------------------------------------
__global__ void __launch_bounds__(256)
round_pre_kernel(const float* __restrict__ X, const float* __restrict__ Wq,
                 const float* __restrict__ Wk, const float* __restrict__ Wv) {
    const size_t i = (size_t)blockIdx.x * blockDim.x + threadIdx.x;   // float4 idx
    const size_t X4 = QKV_STRIDE / 4;                                  // 4194304
    float4 v;
    float4* dst;
    if (i < X4) {
        v = ((const float4*)X)[i];
        dst = (float4*)g_x + i;
    } else {
        const size_t w = i - X4;
        const int p = (int)(w >> 16);
        const size_t off = w & 65535;
        const float* src = (p == 0) ? Wq : (p == 1) ? Wk : Wv;
        v = ((const float4*)src)[off];
        dst = (float4*)g_w + w;
    }
    v.x = roundtf(v.x); v.y = roundtf(v.y);
    v.z = roundtf(v.z); v.w = roundtf(v.w);
    *dst = v;
}

__global__ void __launch_bounds__(256, 2)
qkv_kernel() {
    const int z = blockIdx.z;   // 0=q, 1=k, 2=v(transposed)
    const float* W = g_w + (size_t)z * DIM * DIM;
    if (z == 2)
        gemm_nt<2>(g_x, W, g_qkv + 2 * QKV_STRIDE, DIM, DIM, DIM, DIM, 1.0f);
    else
        gemm_nt<1>(g_x, W, g_qkv + (size_t)z * QKV_STRIDE, DIM, DIM, DIM, DIM, 1.0f);
}

__global__ void __launch_bounds__(256, 2)
scores_kernel() {
    const int b = blockIdx.z;
    gemm_nt<0>(g_qkv + (size_t)b * BATCH_QKV,                 // q[b]
               g_qkv + QKV_STRIDE + (size_t)b * BATCH_QKV,    // k[b]
               g_s + (size_t)b * BATCH_S,
               DIM, DIM, N_SEQ, DIM, 0.044194173824159216f);
}

__global__ void __launch_bounds__(128)
softmax_kernel() {
    const size_t row = blockIdx.x;
    float* p = g_s + row * N_SEQ;
    const int tid = threadIdx.x;

    float4 a = ((const float4*)p)[tid];
    float4 b = ((const float4*)p)[tid + 128];
    float v[8] = {a.x, a.y, a.z, a.w, b.x, b.y, b.z, b.w};

#pragma unroll
    for (int i = 0; i < 8; i++) if (v[i] == 0.0f) v[i] = 1e-10f;  // reference quirk

    float mx = v[0];
#pragma unroll
    for (int i = 1; i < 8; i++) mx = fmaxf(mx, v[i]);
#pragma unroll
    for (int o = 16; o > 0; o >>= 1) mx = fmaxf(mx, __shfl_xor_sync(0xffffffffu, mx, o));
    __shared__ float red[4];
    const int wid = tid >> 5, lane = tid & 31;
    if (lane == 0) red[wid] = mx;
    __syncthreads();
    mx = fmaxf(fmaxf(red[0], red[1]), fmaxf(red[2], red[3]));
    __syncthreads();

    float e[8], s = 0.0f;
#pragma unroll
    for (int i = 0; i < 8; i++) { e[i] = __expf(v[i] - mx); s += e[i]; }
#pragma unroll
    for (int o = 16; o > 0; o >>= 1) s += __shfl_xor_sync(0xffffffffu, s, o);
    if (lane == 0) red[wid] = s;
    __syncthreads();
    s = red[0] + red[1] + red[2] + red[3];
    const float inv = 1.0f / s;

    // store tf32-rounded probabilities (pv consumes raw bits)
    float4 oa = make_float4(roundtf(e[0] * inv), roundtf(e[1] * inv),
                            roundtf(e[2] * inv), roundtf(e[3] * inv));
    float4 ob = make_float4(roundtf(e[4] * inv), roundtf(e[5] * inv),
                            roundtf(e[6] * inv), roundtf(e[7] * inv));
    ((float4*)p)[tid] = oa;
    ((float4*)p)[tid + 128] = ob;
}

__global__ void __launch_bounds__(256, 2)
pv_kernel(float* __restrict__ out) {
    const int b = blockIdx.z;
    gemm_nt<0>(g_s + (size_t)b * BATCH_S,                        // P[b] [1024 x 1024]
               g_qkv + 2 * QKV_STRIDE + (size_t)b * BATCH_QKV,   // V^T[b] [512 x 1024]
               out + (size_t)b * BATCH_QKV,
               N_SEQ, N_SEQ, DIM, N_SEQ, 1.0f);
}

// ---- launch ---------------------------------------------------------------
extern "C" void kernel_launch(void* const* d_in, const int* in_sizes, int n_in,
                              void* d_out, int out_size) {
    const float* X  = (const float*)d_in[0];
    const float* Wq = (const float*)d_in[1];
    const float* Wk = (const float*)d_in[2];
    const float* Wv = (const float*)d_in[3];
    float* out = (float*)d_out;

    cudaFuncSetAttribute(qkv_kernel,    cudaFuncAttributeMaxDynamicSharedMemorySize, SMEM_BYTES);
    cudaFuncSetAttribute(scores_kernel, cudaFuncAttributeMaxDynamicSharedMemorySize, SMEM_BYTES);
    cudaFuncSetAttribute(pv_kernel,     cudaFuncAttributeMaxDynamicSharedMemorySize, SMEM_BYTES);

    round_pre_kernel<<<17152, 256>>>(X, Wq, Wk, Wv);   // (4194304+196608)/256

    dim3 g1(M_TOT / 128, DIM / 128, 3);
    qkv_kernel<<<g1, 256, SMEM_BYTES>>>();

    dim3 g2(N_SEQ / 128, N_SEQ / 128, B_BATCH);
    scores_kernel<<<g2, 256, SMEM_BYTES>>>();

    softmax_kernel<<<M_TOT, 128>>>();

    dim3 g4(N_SEQ / 128, DIM / 128, B_BATCH);
    pv_kernel<<<g4, 256, SMEM_BYTES>>>(out);
}

// round 3
// speedup vs baseline: 1.1844x; 1.1844x over previous
#include <cuda_runtime.h>
#include <cuda_bf16.h>
#include <cstdint>
#include <cstddef>

// ---------------------------------------------------------------------------
// Attention B=32, N=1024, D=512, fp32. tf32 mma.sync GEMMs.
// Contraction dims stored k-PERMUTED in global memory (k=4a+t -> col 8t+a)
// => fragment loads are conflict-free LDS.128, mainloops are cvt-free
// (producer-side tf32 rounding, proven bit-identical in R1/R2).
// ---------------------------------------------------------------------------

#define B_BATCH 32
#define N_SEQ   1024
#define DIM     512
#define M_TOT   (B_BATCH * N_SEQ)
#define QKV_STRIDE ((size_t)M_TOT * DIM)
#define BATCH_QKV  ((size_t)N_SEQ * DIM)
#define BATCH_S    ((size_t)N_SEQ * N_SEQ)

__device__ float g_x[QKV_STRIDE];          // rounded X, d-cols permuted
__device__ float g_w[3 * DIM * DIM];       // rounded W, d-cols permuted
__device__ float g_qkv[3 * QKV_STRIDE];    // q,k: e-cols permuted; v: plain e
__device__ float g_vt[QKV_STRIDE];         // V^T per batch [DIM][N_SEQ], n-cols permuted
__device__ float g_s[B_BATCH * BATCH_S];   // S / P, key-cols permuted

// ---- helpers --------------------------------------------------------------
__device__ __forceinline__ uint32_t f2tf(float x) {
    uint32_t r; asm("cvt.rna.tf32.f32 %0, %1;" : "=r"(r) : "f"(x)); return r;
}
__device__ __forceinline__ float roundtf(float x) { return __uint_as_float(f2tf(x)); }
__device__ __forceinline__ int perm32(int l)  { return ((l & 3) << 3) + (l >> 2); } // k=4a+t -> 8t+a
__device__ __forceinline__ int iperm32(int c) { return ((c & 7) << 2) + (c >> 3); }

__device__ __forceinline__ void mma_16x8x8(float* c, const float* a, float b0f, float b1f) {
    uint32_t a0 = __float_as_uint(a[0]), a1 = __float_as_uint(a[1]);
    uint32_t a2 = __float_as_uint(a[2]), a3 = __float_as_uint(a[3]);
    uint32_t b0 = __float_as_uint(b0f), b1 = __float_as_uint(b1f);
    asm volatile(
        "mma.sync.aligned.m16n8k8.row.col.f32.tf32.tf32.f32 "
        "{%0,%1,%2,%3}, {%4,%5,%6,%7}, {%8,%9}, {%0,%1,%2,%3};"
        : "+f"(c[0]), "+f"(c[1]), "+f"(c[2]), "+f"(c[3])
        : "r"(a0), "r"(a1), "r"(a2), "r"(a3), "r"(b0), "r"(b1));
}

#define CP16(dst_u32, src_ptr) \
    asm volatile("cp.async.cg.shared.global [%0], [%1], 16;" :: "r"(dst_u32), "l"(src_ptr))
#define CP_COMMIT() asm volatile("cp.async.commit_group;")
#define CP_WAIT0()  asm volatile("cp.async.wait_group 0;")
#define CP_WAIT1()  asm volatile("cp.async.wait_group 1;")

// ---- NT GEMM: C[M,N] = alpha*A[M,K]*B[N,K]^T, K-cols permuted in memory ----
// Block 128x128x32, 256 thr, 8 warps (4m x 2n), warp 32x64.
#define TSTRIDE 36
#define TBUF    (128 * TSTRIDE)
#define SMEM_BYTES (4 * TBUF * 4)   // 73728

// EPI: 0 plain float2 | 1 rounded float2 | 2 perm cols + rounded | 3 perm cols plain
template<int EPI>
__device__ __forceinline__ void gemm_nt(const float* __restrict__ A,
                                        const float* __restrict__ B,
                                        float* __restrict__ C,
                                        int lda, int ldb, int ldc,
                                        int K, float alpha) {
    extern __shared__ float smem[];
    float* As = smem;
    float* Bs = smem + 2 * TBUF;

    const int tid  = threadIdx.x;
    const int bm   = blockIdx.x * 128;
    const int bn   = blockIdx.y * 128;
    const int lane = tid & 31;
    const int wid  = tid >> 5;
    const int wm0  = (wid & 3) * 32;
    const int wn0  = (wid >> 2) * 64;
    const int g    = lane >> 2;
    const int t4   = lane & 3;

    const uint32_t as_u = (uint32_t)__cvta_generic_to_shared(As);
    const uint32_t bs_u = (uint32_t)__cvta_generic_to_shared(Bs);

    float acc[2][8][4];
#pragma unroll
    for (int i = 0; i < 2; i++)
#pragma unroll
        for (int j = 0; j < 8; j++)
#pragma unroll
            for (int r = 0; r < 4; r++) acc[i][j][r] = 0.0f;

    auto loadA = [&](int kt, int buf) {
#pragma unroll
        for (int i = 0; i < 4; i++) {
            int c  = tid + i * 256;
            int r  = c >> 3;
            int c4 = (c & 7) * 4;
            uint32_t dst = as_u + (uint32_t)((buf * TBUF + r * TSTRIDE + c4) * 4);
            CP16(dst, A + (size_t)(bm + r) * lda + kt * 32 + c4);
        }
    };
    auto loadB = [&](int kt, int buf) {
#pragma unroll
        for (int i = 0; i < 4; i++) {
            int c  = tid + i * 256;
            int r  = c >> 3;
            int c4 = (c & 7) * 4;
            uint32_t dst = bs_u + (uint32_t)((buf * TBUF + r * TSTRIDE + c4) * 4);
            CP16(dst, B + (size_t)(bn + r) * ldb + kt * 32 + c4);
        }
    };

    auto compute = [&](int buf) {
        const float* Ab = As + buf * TBUF;
        const float* Bb = Bs + buf * TBUF;
        // A fragments for the whole 32-k tile: rows (wm0+16i+g, +8), cols 8t4..8t4+7
        float alo[2][8], ahi[2][8];
#pragma unroll
        for (int i = 0; i < 2; i++) {
            const float* pa = Ab + (wm0 + 16 * i + g) * TSTRIDE + 8 * t4;
            float4 l0 = ((const float4*)pa)[0];
            float4 l1 = ((const float4*)pa)[1];
            const float* ph = pa + 8 * TSTRIDE;
            float4 h0 = ((const float4*)ph)[0];
            float4 h1 = ((const float4*)ph)[1];
            alo[i][0]=l0.x; alo[i][1]=l0.y; alo[i][2]=l0.z; alo[i][3]=l0.w;
            alo[i][4]=l1.x; alo[i][5]=l1.y; alo[i][6]=l1.z; alo[i][7]=l1.w;
            ahi[i][0]=h0.x; ahi[i][1]=h0.y; ahi[i][2]=h0.z; ahi[i][3]=h0.w;
            ahi[i][4]=h1.x; ahi[i][5]=h1.y; ahi[i][6]=h1.z; ahi[i][7]=h1.w;
        }
#pragma unroll
        for (int j = 0; j < 8; j++) {
            const float* pb = Bb + (wn0 + 8 * j + g) * TSTRIDE + 8 * t4;
            float4 b0 = ((const float4*)pb)[0];
            float4 b1 = ((const float4*)pb)[1];
            float bf[8] = {b0.x, b0.y, b0.z, b0.w, b1.x, b1.y, b1.z, b1.w};
#pragma unroll
            for (int ks = 0; ks < 4; ks++) {
                float afr0[4] = {alo[0][2*ks], ahi[0][2*ks], alo[0][2*ks+1], ahi[0][2*ks+1]};
                float afr1[4] = {alo[1][2*ks], ahi[1][2*ks], alo[1][2*ks+1], ahi[1][2*ks+1]};
                mma_16x8x8(acc[0][j], afr0, bf[2*ks], bf[2*ks+1]);
                mma_16x8x8(acc[1][j], afr1, bf[2*ks], bf[2*ks+1]);
            }
        }
    };

    const int KT = K >> 5;
    loadA(0, 0); loadB(0, 0); CP_COMMIT();
    for (int kt = 0; kt < KT; kt++) {
        const int buf = kt & 1;
        if (kt + 1 < KT) {
            loadA(kt + 1, buf ^ 1); loadB(kt + 1, buf ^ 1); CP_COMMIT();
            CP_WAIT1();
        } else {
            CP_WAIT0();
        }
        __syncthreads();
        compute(buf);
        __syncthreads();
    }

    // epilogue
#pragma unroll
    for (int i = 0; i < 2; i++) {
#pragma unroll
        for (int j = 0; j < 8; j++) {
            const int r0 = bm + wm0 + i * 16 + g;
            const int c0 = bn + wn0 + j * 8 + 2 * t4;
            float v00 = acc[i][j][0] * alpha, v01 = acc[i][j][1] * alpha;
            float v10 = acc[i][j][2] * alpha, v11 = acc[i][j][3] * alpha;
            if (EPI == 0) {
                *(float2*)&C[(size_t)r0 * ldc + c0] = make_float2(v00, v01);
                *(float2*)&C[(size_t)(r0 + 8) * ldc + c0] = make_float2(v10, v11);
            } else if (EPI == 1) {
                *(float2*)&C[(size_t)r0 * ldc + c0] =
                    make_float2(roundtf(v00), roundtf(v01));
                *(float2*)&C[(size_t)(r0 + 8) * ldc + c0] =
                    make_float2(roundtf(v10), roundtf(v11));
            } else {
                const int blk = c0 & ~31;
                const int p0 = blk + perm32(c0 & 31);
                const int p1 = blk + perm32((c0 + 1) & 31);
                if (EPI == 2) {
                    C[(size_t)r0 * ldc + p0]       = roundtf(v00);
                    C[(size_t)r0 * ldc + p1]       = roundtf(v01);
                    C[(size_t)(r0 + 8) * ldc + p0] = roundtf(v10);
                    C[(size_t)(r0 + 8) * ldc + p1] = roundtf(v11);
                } else {
                    C[(size_t)r0 * ldc + p0]       = v00;
                    C[(size_t)r0 * ldc + p1]       = v01;
                    C[(size_t)(r0 + 8) * ldc + p0] = v10;
                    C[(size_t)(r0 + 8) * ldc + p1] = v11;
                }
            }
        }
    }
}

// ---- kernels --------------------------------------------------------------
// Pre-pass: round to tf32 and permute d-cols of X and Wq/Wk/Wv.
__global__ void __launch_bounds__(256)
round_perm_kernel(const float* __restrict__ X, const float* __restrict__ Wq,
                  const float* __restrict__ Wk, const float* __restrict__ Wv) {
    const size_t i = (size_t)blockIdx.x * blockDim.x + threadIdx.x;   // float4 index
    const size_t X4 = QKV_STRIDE / 4;
    const float* src;
    float4* dst;
    size_t flat4;
    if (i < X4) {
        flat4 = i * 4;
        src = X + (flat4 >> 9) * DIM;
        dst = (float4*)g_x + i;
    } else {
        const size_t w = i - X4;
        const int p = (int)(w >> 16);
        flat4 = (w & 65535) * 4;
        const float* Wp = (p == 0) ? Wq : (p == 1) ? Wk : Wv;
        src = Wp + (flat4 >> 9) * DIM;
        dst = (float4*)g_w + w;
    }
    const int cb = (int)(flat4 & 511);
    float o[4];
#pragma unroll
    for (int m = 0; m < 4; m++) {
        const int c = cb + m;
        o[m] = roundtf(src[(c & ~31) + iperm32(c & 31)]);
    }
    *dst = make_float4(o[0], o[1], o[2], o[3]);
}

__global__ void __launch_bounds__(256, 2)
qkv_kernel() {
    const int z = blockIdx.z;
    const float* W = g_w + (size_t)z * DIM * DIM;
    if (z == 2)      // V: plain e cols, rounded
        gemm_nt<1>(g_x, W, g_qkv + 2 * QKV_STRIDE, DIM, DIM, DIM, DIM, 1.0f);
    else             // q,k: e cols permuted (scores contraction), rounded
        gemm_nt<2>(g_x, W, g_qkv + (size_t)z * QKV_STRIDE, DIM, DIM, DIM, DIM, 1.0f);
}

// V[b][n][e] -> VT[b][e][perm(n)]
__global__ void __launch_bounds__(256)
transpose_v_kernel() {
    __shared__ float s[32][33];
    const int b  = blockIdx.z;
    const int e0 = blockIdx.x * 32;
    const int n0 = blockIdx.y * 32;
    const int tx = threadIdx.x, ty = threadIdx.y;
    const float* v = g_qkv + 2 * QKV_STRIDE + (size_t)b * BATCH_QKV;
    float* vt = g_vt + (size_t)b * BATCH_QKV;
#pragma unroll
    for (int k = 0; k < 4; k++)
        s[ty + 8 * k][tx] = v[(size_t)(n0 + ty + 8 * k) * DIM + e0 + tx];
    __syncthreads();
    const int pc = n0 + perm32(tx);
#pragma unroll
    for (int k = 0; k < 4; k++)
        vt[(size_t)(e0 + ty + 8 * k) * N_SEQ + pc] = s[tx][ty + 8 * k];
}

__global__ void __launch_bounds__(256, 2)
scores_kernel() {
    const int b = blockIdx.z;
    gemm_nt<3>(g_qkv + (size_t)b * BATCH_QKV,                 // q[b]
               g_qkv + QKV_STRIDE + (size_t)b * BATCH_QKV,    // k[b]
               g_s + (size_t)b * BATCH_S,
               DIM, DIM, N_SEQ, DIM, 0.044194173824159216f);  // key-cols permuted out
}

__global__ void __launch_bounds__(128)
softmax_kernel() {   // permutation-invariant row softmax; stores rounded P
    const size_t row = blockIdx.x;
    float* p = g_s + row * N_SEQ;
    const int tid = threadIdx.x;

    float4 a = ((const float4*)p)[tid];
    float4 b = ((const float4*)p)[tid + 128];
    float v[8] = {a.x, a.y, a.z, a.w, b.x, b.y, b.z, b.w};
#pragma unroll
    for (int i = 0; i < 8; i++) if (v[i] == 0.0f) v[i] = 1e-10f;  // reference quirk

    float mx = v[0];
#pragma unroll
    for (int i = 1; i < 8; i++) mx = fmaxf(mx, v[i]);
#pragma unroll
    for (int o = 16; o > 0; o >>= 1) mx = fmaxf(mx, __shfl_xor_sync(0xffffffffu, mx, o));
    __shared__ float red[4];
    const int wid = tid >> 5, lane = tid & 31;
    if (lane == 0) red[wid] = mx;
    __syncthreads();
    mx = fmaxf(fmaxf(red[0], red[1]), fmaxf(red[2], red[3]));
    __syncthreads();

    float e[8], s = 0.0f;
#pragma unroll
    for (int i = 0; i < 8; i++) { e[i] = __expf(v[i] - mx); s += e[i]; }
#pragma unroll
    for (int o = 16; o > 0; o >>= 1) s += __shfl_xor_sync(0xffffffffu, s, o);
    if (lane == 0) red[wid] = s;
    __syncthreads();
    s = red[0] + red[1] + red[2] + red[3];
    const float inv = 1.0f / s;

    ((float4*)p)[tid] = make_float4(roundtf(e[0]*inv), roundtf(e[1]*inv),
                                    roundtf(e[2]*inv), roundtf(e[3]*inv));
    ((float4*)p)[tid + 128] = make_float4(roundtf(e[4]*inv), roundtf(e[5]*inv),
                                          roundtf(e[6]*inv), roundtf(e[7]*inv));
}

__global__ void __launch_bounds__(256, 2)
pv_kernel(float* __restrict__ out) {
    const int b = blockIdx.z;
    gemm_nt<0>(g_s + (size_t)b * BATCH_S,         // P[b] [1024 x 1024perm]
               g_vt + (size_t)b * BATCH_QKV,      // V^T[b] [512 x 1024perm]
               out + (size_t)b * BATCH_QKV,
               N_SEQ, N_SEQ, DIM, N_SEQ, 1.0f);
}

// ---- launch ---------------------------------------------------------------
extern "C" void kernel_launch(void* const* d_in, const int* in_sizes, int n_in,
                              void* d_out, int out_size) {
    const float* X  = (const float*)d_in[0];
    const float* Wq = (const float*)d_in[1];
    const float* Wk = (const float*)d_in[2];
    const float* Wv = (const float*)d_in[3];
    float* out = (float*)d_out;

    cudaFuncSetAttribute(qkv_kernel,    cudaFuncAttributeMaxDynamicSharedMemorySize, SMEM_BYTES);
    cudaFuncSetAttribute(scores_kernel, cudaFuncAttributeMaxDynamicSharedMemorySize, SMEM_BYTES);
    cudaFuncSetAttribute(pv_kernel,     cudaFuncAttributeMaxDynamicSharedMemorySize, SMEM_BYTES);

    round_perm_kernel<<<17152, 256>>>(X, Wq, Wk, Wv);

    dim3 g1(M_TOT / 128, DIM / 128, 3);
    qkv_kernel<<<g1, 256, SMEM_BYTES>>>();

    dim3 gt(DIM / 32, N_SEQ / 32, B_BATCH);
    transpose_v_kernel<<<gt, dim3(32, 8)>>>();

    dim3 g2(N_SEQ / 128, N_SEQ / 128, B_BATCH);
    scores_kernel<<<g2, 256, SMEM_BYTES>>>();

    softmax_kernel<<<M_TOT, 128>>>();

    dim3 g4(N_SEQ / 128, DIM / 128, B_BATCH);
    pv_kernel<<<g4, 256, SMEM_BYTES>>>(out);
}